// round 15
// baseline (speedup 1.0000x reference)
#include <cuda_runtime.h>
#include <cuda_bf16.h>

#define BATCH 16
#define LEN   2048
#define TPB   256
#define NW    8
#define CHUNK 256             // elements per warp in compaction
#define KPW   8
#define GAMMA 0.1f
#define T9    9               // positive tiles
#define TILE  128
#define PADP  (T9 * TILE)     // 1152 padded positive length
#define PPU   45              // T9*(T9+1)/2 unordered tile pairs
#define PNU   9               // PN a-slices
#define NU    (PPU + PNU)     // 54 units per batch
#define PAD_X (-1.0f)
#define PAD_F (1.0e6f)

__device__ float    g_Px[BATCH][PADP];
__device__ float    g_Pf[BATCH][PADP];
__device__ float    g_Nx[BATCH][LEN];
__device__ int      g_cnt[BATCH];
__device__ float    g_partial[BATCH * NU];
__device__ float    g_bsum[BATCH];
__device__ unsigned g_doneB[BATCH];
__device__ unsigned g_done = 0;

static __device__ __forceinline__ float sigmoidf(float v) {
    return 1.0f / (1.0f + __expf(-v));
}
static __device__ __forceinline__ float rcpf(float s) {
    float r; asm("rcp.approx.f32 %0, %1;" : "=f"(r) : "f"(s)); return r;
}

// ================= Kernel 1: per-batch compaction -> padded global lists
__global__ __launch_bounds__(TPB) void compact_kernel(
        const float* __restrict__ inp,
        const int*   __restrict__ tgt,
        const float* __restrict__ freq) {
    const int b = blockIdx.x;
    const int tid = threadIdx.x;
    const int w = tid >> 5, lane = tid & 31;
    __shared__ int s_cntP[NW];

    const int rowoff = b * LEN;

    unsigned bal[KPW];
    float    xv[KPW];
    int pc = 0;
#pragma unroll
    for (int k = 0; k < KPW; k++) {
        int i = w * CHUNK + k * 32 + lane;
        int t = tgt[rowoff + i];
        xv[k] = inp[rowoff + i];
        bal[k] = __ballot_sync(0xffffffffu, t != 0);
        pc += __popc(bal[k]);
    }
    if (lane == 0) s_cntP[w] = pc;
    __syncthreads();

    int prefP = 0, cp = 0;
#pragma unroll
    for (int ww = 0; ww < NW; ww++) {
        int c = s_cntP[ww];
        if (ww < w) prefP += c;
        cp += c;
    }
    const int prefN = w * CHUNK - prefP;

    const unsigned lt = (1u << lane) - 1u;
    int baseP = 0, baseN = 0;
#pragma unroll
    for (int k = 0; k < KPW; k++) {
        int i = w * CHUNK + k * 32 + lane;
        float x = sigmoidf(xv[k]);
        unsigned m = bal[k];
        if ((m >> lane) & 1u) {
            int pos = prefP + baseP + __popc(m & lt);
            g_Px[b][pos] = x;
            g_Pf[b][pos] = freq[i];
        } else {
            int pos = prefN + baseN + (lane - __popc(m & lt));
            g_Nx[b][pos] = x;
        }
        int c = __popc(m);
        baseP += c;
        baseN += 32 - c;
    }
    // Pad positives so ALL pad-involved PP terms are exactly zero:
    // fd = fa - 1e6 < 0 while d = xa - (-1) > 0  ->  relu(fd*d) = 0.
    for (int i = cp + tid; i < PADP; i += TPB) {
        g_Px[b][i] = PAD_X;
        g_Pf[b][i] = PAD_F;
    }
    if (tid == 0) g_cnt[b] = cp;
}

// ================= Kernel 2: tile-pair units + PN units + 2-level reduction
__global__ __launch_bounds__(TPB, 8) void unit_kernel(float* __restrict__ out,
                                                      int out_size) {
    const int u   = blockIdx.x;           // 0..44 PP tile pair, 45..53 PN slice
    const int b   = blockIdx.y;
    const int tid = threadIdx.x;
    const int w   = tid >> 5, lane = tid & 31;

    __shared__ float  sN[LEN];            // PN: negative x list (PP: unused)
    __shared__ float2 sB[TILE];           // PP: j-tile (x_j, f_j)
    __shared__ float  red[TPB];
    __shared__ int    s_flag;

    const int cp = g_cnt[b];
    float total = 0.0f;

    if (u < PPU) {
        // ---- map u -> unordered tile pair (t1 <= t2)
        int t1 = 0, r = u;
        while (r >= T9 - t1) { r -= T9 - t1; t1++; }
        const int t2 = t1 + r;

        // j-tile into smem
        for (int i = tid; i < TILE; i += TPB)
            sB[i] = make_float2(g_Px[b][t2 * TILE + i], g_Pf[b][t2 * TILE + i]);
        __syncthreads();

        // 4 a-lanes from tile t1 (coalesced)
        float xa[4], fa[4], acc[4];
#pragma unroll
        for (int k = 0; k < 4; k++) {
            int ai = t1 * TILE + lane + 32 * k;
            xa[k] = g_Px[b][ai];
            fa[k] = g_Pf[b][ai];
            acc[k] = 0.0f;
        }
        // warp w covers j in [16w, 16w+16) -- static bounds, fully unrolled
        const int j0 = w * 16;
#pragma unroll
        for (int jj = 0; jj < 16; jj++) {
            float2 t = sB[j0 + jj];           // warp-broadcast LDS.64
#pragma unroll
            for (int k = 0; k < 4; k++) {
                float d  = xa[k] - t.x;
                float fd = fa[k] - t.y;
                float s  = fa[k] + t.y;       // > 0 always
                acc[k] = fmaf(fmaxf(fd * d, 0.0f), rcpf(s), acc[k]);
            }
        }
        float sum = (acc[0] + acc[1]) + (acc[2] + acc[3]);
        total = (t1 == t2) ? sum : 2.0f * sum;   // symmetry doubling
    } else {
        // ---- PN unit: a-slice (u-PPU) vs all negatives, max identity
        const int sl = u - PPU;
        const int cn = LEN - cp;
        for (int i = tid; i < cn; i += TPB) sN[i] = g_Nx[b][i];
        __syncthreads();

        float xa[4], accM[4], ok[4];
#pragma unroll
        for (int k = 0; k < 4; k++) {
            int ai = sl * TILE + lane + 32 * k;
            xa[k] = g_Px[b][ai];              // pad a's get x=-1 (guarded out)
            ok[k] = (ai < cp) ? 1.0f : 0.0f;
            accM[k] = 0.0f;
        }
        const int j0 = (w * cn) >> 3;         // warp j-chunk [j0, j1)
        const int j1 = ((w + 1) * cn) >> 3;
#pragma unroll 4
        for (int j = j0; j < j1; j++) {
            float xj = sN[j];
#pragma unroll
            for (int k = 0; k < 4; k++)
                accM[k] += fmaxf(xj, xa[k]);  // FMNMX + FADD only
        }
        const float len = (float)(j1 - j0);
        float sum = 0.0f;
#pragma unroll
        for (int k = 0; k < 4; k++)
            sum += ok[k] * fmaf(-len, xa[k], accM[k]);  // = sum relu(xj-xa)
        total = GAMMA * sum;
    }

    // ---- Deterministic in-block tree reduction
    red[tid] = total;
    __syncthreads();
    for (int s = TPB / 2; s > 0; s >>= 1) {
        if (tid < s) red[tid] += red[tid + s];
        __syncthreads();
    }
    if (tid == 0) g_partial[b * NU + u] = red[0];

    // ---- Level 1: per-batch ticket (54); batch-last reduces in fixed order
    __threadfence();
    if (tid == 0) {
        unsigned old = atomicAdd(&g_doneB[b], 1u);
        if (old == NU - 1) {
            __threadfence();
            float s = 0.0f;
            for (int i = 0; i < NU; i++) s += g_partial[b * NU + i];
            g_bsum[b] = s;
            g_doneB[b] = 0;                   // self-reset for graph replay
            __threadfence();
            unsigned old2 = atomicAdd(&g_done, 1u);
            s_flag = (old2 == BATCH - 1) ? 1 : 0;
        } else {
            s_flag = 0;
        }
    }
    __syncthreads();
    if (s_flag && tid == 0) {
        __threadfence();
        float s = 0.0f;
        for (int i = 0; i < BATCH; i++) s += g_bsum[i];   // fixed order
        float r = s / (float)BATCH;
        for (int i = 0; i < out_size; i++) out[i] = r;
        g_done = 0;                           // self-reset for graph replay
    }
}

extern "C" void kernel_launch(void* const* d_in, const int* in_sizes, int n_in,
                              void* d_out, int out_size) {
    const float* inp  = (const float*)d_in[0];   // [16, 2048] f32
    const int*   tgt  = (const int*)d_in[1];     // [16, 2048] i32
    const float* freq = (const float*)d_in[2];   // [2048] f32
    float* out = (float*)d_out;

    compact_kernel<<<BATCH, TPB>>>(inp, tgt, freq);
    unit_kernel<<<dim3(NU, BATCH), TPB>>>(out, out_size);
}

// round 17
// speedup vs baseline: 1.1648x; 1.1648x over previous
#include <cuda_runtime.h>
#include <cuda_bf16.h>

#define BATCH 16
#define LEN   2048
#define JT    37              // 37*16 = 592 blocks
#define TPB   256
#define NW    8
#define CHUNK 256             // elements per warp in compaction
#define KPW   8               // ballot sub-iterations per warp
#define GAMMA 0.1f
#define MAXM  56              // max j-slots per block
#define NBLK  (BATCH * JT)

__device__ float g_partial[NBLK];
__device__ unsigned g_done = 0;       // self-resetting ticket counter

static __device__ __forceinline__ float sigmoidf(float v) {
    return 1.0f / (1.0f + __expf(-v));
}
static __device__ __forceinline__ float rcpf(float s) {
    float r; asm("rcp.approx.f32 %0, %1;" : "=f"(r) : "f"(s)); return r;
}

// One register-blocked pass over KR*256 a-lanes vs the block's j-window.
// PN uses the max identity: sum_j relu(xj-xa) = sum_j max(xj,xa) - nN*xa.
// Zero-padded lists make loads safe; GUARD zeroes pad-lane results.
template <int KR, bool GUARD>
static __device__ __forceinline__ float pair_pass(
        const float*  __restrict__ sPx, const float* __restrict__ sPf,
        const float4* __restrict__ wPP, const float* __restrict__ wNx,
        int nP, int nN, int abase, int tid, int cp) {
    float xa[KR], fa[KR], accP[KR], accM[KR];
#pragma unroll
    for (int k = 0; k < KR; k++) {
        int ai = abase + tid + k * TPB;
        xa[k] = sPx[ai]; fa[k] = sPf[ai];
        accP[k] = 0.0f; accM[k] = 0.0f;
    }
#pragma unroll 4
    for (int j = 0; j < nP; j++) {
        float4 t = wPP[j];                    // 1 LDS.128 amortized over KR lanes
#pragma unroll
        for (int k = 0; k < KR; k++) {
            float d  = xa[k] + t.x;           // x_a - x_j
            float fd = fa[k] + t.y;           // f_a - f_j
            float s  = fa[k] + t.z;           // f_a + f_j > 0
            accP[k] = fmaf(fmaxf(fd * d, 0.0f), rcpf(s), accP[k]);
        }
    }
#pragma unroll 4
    for (int j = 0; j < nN; j++) {
        float xj = wNx[j];
#pragma unroll
        for (int k = 0; k < KR; k++)
            accM[k] += fmaxf(xj, xa[k]);      // FMNMX + FADD only
    }
    float tot = 0.0f;
    const float fnN = (float)nN;
#pragma unroll
    for (int k = 0; k < KR; k++) {
        float pn = fmaf(-fnN, xa[k], accM[k]);      // = sum relu(xj - xa)
        float v  = fmaf(GAMMA, pn, accP[k]);
        if (GUARD) v *= (abase + tid + k * TPB < cp) ? 1.0f : 0.0f;
        tot += v;
    }
    return tot;
}

// ============ Single fused kernel: compact -> pairs -> global reduction
// 6 blocks/SM (42-reg cap) x 18.2KB smem = 109KB/SM -> needs raised carveout.
__global__ __launch_bounds__(TPB, 6) void fused_kernel(
        const float* __restrict__ inp,
        const int*   __restrict__ tgt,
        const float* __restrict__ freq,
        float* __restrict__ out, int out_size) {
    const int jt  = blockIdx.x;
    const int b   = blockIdx.y;
    const int tid = threadIdx.x;
    const int w   = tid >> 5, lane = tid & 31;

    __shared__ float  sPx[LEN];
    __shared__ float  sPf[LEN];
    __shared__ int    s_cntP[NW];
    __shared__ float4 wPP[MAXM];   // (-x_s, -f_s, f_s, 0) positive window slots
    __shared__ float  wNx[MAXM];   // x_j negative window slots
    __shared__ float  red[TPB / 32];
    __shared__ int    s_last;

    const int rowoff = b * LEN;

    // ---- Compaction pass A: ballots + value prefetch (16 loads in flight)
    unsigned bal[KPW];
    float    xv[KPW];
    int pc = 0;
#pragma unroll
    for (int k = 0; k < KPW; k++) {
        int i = w * CHUNK + k * 32 + lane;
        int t = tgt[rowoff + i];
        xv[k] = inp[rowoff + i];
        bal[k] = __ballot_sync(0xffffffffu, t != 0);
        pc += __popc(bal[k]);
    }
    if (lane == 0) s_cntP[w] = pc;
    __syncthreads();

    int prefP = 0, cp = 0;
#pragma unroll
    for (int ww = 0; ww < NW; ww++) {
        int c = s_cntP[ww];
        if (ww < w) prefP += c;
        cp += c;
    }
    const int prefN = w * CHUNK - prefP;

    // Window geometry: slots s = jt + JT*m over concatenated [P(0..cp) | N]
    const int M  = (LEN - 1 - jt) / JT + 1;
    int mP = 0;
    if (cp > jt) { mP = (cp - jt + JT - 1) / JT; if (mP > M) mP = M; }
    const int s0    = jt + JT * mP;      // first negative window slot (global)
    const int posN0 = s0 - cp;           // its index in the negative list (>=0)

    // ---- Compaction pass B: scatter into shared lists + direct window writes
    const unsigned lt = (1u << lane) - 1u;
    int baseP = 0, baseN = 0;
#pragma unroll
    for (int k = 0; k < KPW; k++) {
        int i = w * CHUNK + k * 32 + lane;
        float x = sigmoidf(xv[k]);
        unsigned m = bal[k];
        if ((m >> lane) & 1u) {
            int pos = prefP + baseP + __popc(m & lt);
            float f = freq[i];
            sPx[pos] = x;
            sPf[pos] = f;
            int r = pos - jt;
            if (r >= 0 && r % JT == 0)                   // window P slot
                wPP[r / JT] = make_float4(-x, -f, f, 0.0f);
        } else {
            int pos = prefN + baseN + (lane - __popc(m & lt));
            int r = pos - posN0;
            if (r >= 0 && r % JT == 0) {                 // window N slot
                int wi = r / JT;
                if (wi < M - mP) wNx[wi] = x;
            }
        }
        int c = __popc(m);
        baseP += c;
        baseN += 32 - c;
    }
    const int cpR = ((cp + TPB - 1) / TPB) * TPB;
    // Zero-pad positives up to pass granularity
    for (int i = cp + tid; i < cpR; i += TPB) {
        sPx[i] = 0.0f;
        sPf[i] = 0.0f;
    }
    __syncthreads();
    const int nP = mP, nN = M - mP;

    float total = 0.0f;

    // Full unguarded KR=4 passes while more than 5*TPB a's remain
    int abase = 0, rem = cp;
    while (rem > 5 * TPB) {
        total += pair_pass<4, false>(sPx, sPf, wPP, wNx, nP, nN, abase, tid, cp);
        abase += 4 * TPB;
        rem   -= 4 * TPB;
    }
    // One guarded adaptive pass covers the remainder (rem in 1..1280)
    switch ((rem + TPB - 1) / TPB) {
        case 1: total += pair_pass<1, true>(sPx, sPf, wPP, wNx, nP, nN, abase, tid, cp); break;
        case 2: total += pair_pass<2, true>(sPx, sPf, wPP, wNx, nP, nN, abase, tid, cp); break;
        case 3: total += pair_pass<3, true>(sPx, sPf, wPP, wNx, nP, nN, abase, tid, cp); break;
        case 4: total += pair_pass<4, true>(sPx, sPf, wPP, wNx, nP, nN, abase, tid, cp); break;
        case 5: total += pair_pass<5, true>(sPx, sPf, wPP, wNx, nP, nN, abase, tid, cp); break;
        default: break;   // rem == 0
    }

    // ---- Deterministic reduction: shuffle within warp, tree across warps
#pragma unroll
    for (int off = 16; off > 0; off >>= 1)
        total += __shfl_down_sync(0xffffffffu, total, off);
    if (lane == 0) red[w] = total;
    __syncthreads();
    if (w == 0) {
        float v = (lane < NW) ? red[lane] : 0.0f;
#pragma unroll
        for (int off = 4; off > 0; off >>= 1)
            v += __shfl_down_sync(0xffffffffu, v, off);
        if (lane == 0) g_partial[b * JT + jt] = v;
    }

    // ---- Fused final reduction: last block sums all partials in fixed order
    __threadfence();
    if (tid == 0) {
        unsigned old = atomicAdd(&g_done, 1u);
        s_last = (old == NBLK - 1) ? 1 : 0;
    }
    __syncthreads();
    if (s_last) {
        float s = 0.0f;
        for (int i = tid; i < NBLK; i += TPB) s += g_partial[i];
#pragma unroll
        for (int off = 16; off > 0; off >>= 1)
            s += __shfl_down_sync(0xffffffffu, s, off);
        if (lane == 0) red[w] = s;
        __syncthreads();
        if (w == 0) {
            float v = (lane < NW) ? red[lane] : 0.0f;
#pragma unroll
            for (int off = 4; off > 0; off >>= 1)
                v += __shfl_down_sync(0xffffffffu, v, off);
            if (lane == 0) {
                float r = v / (float)BATCH;
                for (int i = 0; i < out_size; i++) out[i] = r;
                g_done = 0;             // self-reset for graph replay
            }
        }
    }
}

extern "C" void kernel_launch(void* const* d_in, const int* in_sizes, int n_in,
                              void* d_out, int out_size) {
    const float* inp  = (const float*)d_in[0];   // [16, 2048] f32
    const int*   tgt  = (const int*)d_in[1];     // [16, 2048] i32
    const float* freq = (const float*)d_in[2];   // [2048] f32
    float* out = (float*)d_out;

    // Raise the shared-memory carveout so 6 blocks x 18.2KB fit per SM.
    // Host-side attribute set: idempotent, no allocation, not a stream op.
    cudaFuncSetAttribute(fused_kernel,
                         cudaFuncAttributePreferredSharedMemoryCarveout, 100);

    fused_kernel<<<dim3(JT, BATCH), TPB>>>(inp, tgt, freq, out, out_size);
}